// round 1
// baseline (speedup 1.0000x reference)
#include <cuda_runtime.h>

// SigKerMMD: 3 gram blocks (XX, XY, YY) of 64x64 pairs, each pair:
//   32x32 RBF gram -> 31x31 second difference -> 62x62 Goursat PDE -> corner value.
// out = (sum_XX - 2*sum_XY + sum_YY) / 4096
//
// One warp per pair. Wavefront PDE: thread t owns columns 2t+1, 2t+2 (t=0..30).
// Both columns / both row-pairs share the same dyadic increment diff[(i-1)>>1][t],
// so each thread reads only its own diff column (conflict-free shared).

#define WARPS_PER_BLOCK 4
#define THREADS_PER_BLOCK (WARPS_PER_BLOCK * 32)
#define NPAIRS 12288          // 3 * 64 * 64
#define SEQ 32
#define CH 5
#define SEQCH (SEQ * CH)      // 160

__device__ float g_partial[NPAIRS];

__global__ __launch_bounds__(THREADS_PER_BLOCK)
void sig_pde_kernel(const float* __restrict__ x,
                    const float* __restrict__ y,
                    const float* __restrict__ sig)
{
    __shared__ float sh_xa[WARPS_PER_BLOCK][SEQCH];
    __shared__ float sh_xn[WARPS_PER_BLOCK][SEQ];
    __shared__ float sh_diff[WARPS_PER_BLOCK][31][32];  // [row][col], col==lane -> bank==lane

    const int warp = threadIdx.x >> 5;
    const int lane = threadIdx.x & 31;
    const int w = blockIdx.x * WARPS_PER_BLOCK + warp;     // pair id 0..12287

    const int seg = w >> 12;          // 0=XX, 1=XY, 2=YY
    const int p   = w & 4095;
    const int a   = p >> 6;
    const int b   = p & 63;

    // channel scales for mu = [x0, x1*s0, x2*s1, x3*s2, x4*s3]
    float cs[CH];
    cs[0] = 1.0f;
    cs[1] = sig[0]; cs[2] = sig[1]; cs[3] = sig[2]; cs[4] = sig[3];

    const float* Aptr = ((seg < 2) ? x : y) + a * SEQCH;
    const bool   Ascale = (seg < 2);
    const float* Bptr = ((seg == 0) ? x : y) + b * SEQCH;
    const bool   Bscale = (seg == 0);

    // ---- load A sequence (possibly sigma-scaled) into shared ----
    #pragma unroll
    for (int idx = lane; idx < SEQCH; idx += 32) {
        float v = Aptr[idx];
        if (Ascale) v *= cs[idx % CH];
        sh_xa[warp][idx] = v;
    }
    __syncwarp();

    // ---- per-row squared norms of A ----
    {
        float s = 0.0f;
        #pragma unroll
        for (int c = 0; c < CH; c++) {
            float v = sh_xa[warp][lane * CH + c];
            s += v * v;
        }
        sh_xn[warp][lane] = s;
    }

    // ---- B column (lane n) into registers ----
    float yb[CH];
    float yn = 0.0f;
    #pragma unroll
    for (int c = 0; c < CH; c++) {
        float v = Bptr[lane * CH + c];
        if (Bscale) v *= cs[c];
        yb[c] = v;
        yn += v * v;
    }
    __syncwarp();

    // ---- gram column + m-direction differences -> shared diff ----
    // colDiff[m-1][n] = G[m][n]-G[m-1][n];  diff[i][j] = colDiff[i][j+1]-colDiff[i][j]
    // folded scale: /4 for dyadic order 1
    float gprev = 0.0f;
    #pragma unroll 4
    for (int m = 0; m < SEQ; m++) {
        float dot = 0.0f;
        #pragma unroll
        for (int c = 0; c < CH; c++)
            dot = fmaf(sh_xa[warp][m * CH + c], yb[c], dot);
        float d2 = sh_xn[warp][m] + yn - 2.0f * dot;
        float g = __expf(-d2);          // RBF_SIGMA = 1.0
        if (m > 0) {
            float cd  = g - gprev;
            float cdn = __shfl_down_sync(0xffffffffu, cd, 1);
            if (lane < 31)
                sh_diff[warp][m - 1][lane] = (cdn - cd) * 0.25f;
        }
        gprev = g;
    }
    __syncwarp();

    // ---- wavefront PDE ----
    // K is (63x63), K[0][*]=K[*][0]=1.
    // K[i][j] = (K[i][j-1]+K[i-1][j])*(1+a/2+a^2/12) - K[i-1][j-1]*(1-a^2/12),
    //   a = diff[(i-1)>>1][(j-1)>>1]
    // thread t: cols j1=2t+1, j2=2t+2; step s computes row i = s - t + 1.
    float k1  = 1.0f;   // K[i_last][2t+1]
    float k2  = 1.0f;   // K[i_last][2t+2]
    float k2p = 1.0f;   // K[i_last-1][2t+2]

    for (int s = 0; s < 92; s++) {
        float inL = __shfl_up_sync(0xffffffffu, k2,  1);  // K[i][2t]   from t-1
        float inD = __shfl_up_sync(0xffffffffu, k2p, 1);  // K[i-1][2t] from t-1
        if (lane == 0) { inL = 1.0f; inD = 1.0f; }        // left boundary
        int i = s - lane + 1;
        if (lane < 31 && (unsigned)(i - 1) < 62u) {
            float aa = sh_diff[warp][(i - 1) >> 1][lane];
            float a2 = aa * aa * (1.0f / 12.0f);
            float c1 = 1.0f + 0.5f * aa + a2;
            float c2 = 1.0f - a2;
            float n1 = (inL + k1) * c1 - inD * c2;
            float n2 = (n1  + k2) * c1 - k1  * c2;
            k2p = k2;
            k2  = n2;
            k1  = n1;
        }
    }

    // lane 30 finished row 62 at step 91 -> k2 = K[62][62]
    if (lane == 30) {
        float wgt = (seg == 1) ? -2.0f : 1.0f;
        g_partial[w] = wgt * k2;
    }
}

__global__ void sig_reduce_kernel(float* __restrict__ out)
{
    __shared__ float sh[256];
    float s = 0.0f;
    for (int i = threadIdx.x; i < NPAIRS; i += 256)
        s += g_partial[i];
    sh[threadIdx.x] = s;
    __syncthreads();
    #pragma unroll
    for (int off = 128; off > 0; off >>= 1) {
        if (threadIdx.x < off) sh[threadIdx.x] += sh[threadIdx.x + off];
        __syncthreads();
    }
    if (threadIdx.x == 0)
        out[0] = sh[0] * (1.0f / 4096.0f);
}

extern "C" void kernel_launch(void* const* d_in, const int* in_sizes, int n_in,
                              void* d_out, int out_size)
{
    // Expected order: x [64*32*5], y [64*32*5], sigma_param [4].
    // Pick sigma defensively by element count.
    const float* x = nullptr;
    const float* yy = nullptr;
    const float* sp = nullptr;
    for (int i = 0; i < n_in; i++) {
        if (in_sizes[i] == CH - 1) { sp = (const float*)d_in[i]; }
        else if (!x)               { x  = (const float*)d_in[i]; }
        else if (!yy)              { yy = (const float*)d_in[i]; }
    }

    dim3 grid(NPAIRS / WARPS_PER_BLOCK);
    sig_pde_kernel<<<grid, THREADS_PER_BLOCK>>>(x, yy, sp);
    sig_reduce_kernel<<<1, 256>>>((float*)d_out);
}